// round 1
// baseline (speedup 1.0000x reference)
#include <cuda_runtime.h>
#include <cstdint>

// ---------------- problem constants ----------------
#define NN   50000
#define NE   500000
#define DD   128
#define DEA  16
#define DINP 64
#define NLAY 4

// folded-weight buffer layout (floats, per layer)
#define LSTR     100864
#define WM1_OFF  0
#define BM1_OFF  34816
#define WM2_OFF  34944
#define BM2_OFF  51328
#define WU1_OFF  51456
#define BU1_OFF  84224
#define WU2_OFF  84352
#define BU2_OFF  100736

// ---------------- device scratch (no allocs allowed) ----------------
__device__ __align__(16) float g_h[(size_t)NN * DD];
__device__ __align__(16) float g_agg[(size_t)NN * DD];
__device__ __align__(16) float g_wf[(size_t)NLAY * LSTR];

// ---------------- zero agg ----------------
__global__ void zero_agg_kernel() {
    int i = blockIdx.x * blockDim.x + threadIdx.x;
    float4 z = make_float4(0.f, 0.f, 0.f, 0.f);
    if (i < NN * DD / 4) reinterpret_cast<float4*>(g_agg)[i] = z;
}

// ---------------- fold BN into linear ----------------
__global__ void fold_kernel(const float* __restrict__ W, const float* __restrict__ b,
                            const float* __restrict__ g, const float* __restrict__ be,
                            const float* __restrict__ m, const float* __restrict__ v,
                            int wdst, int bdst, int K) {
    int i = blockIdx.x * blockDim.x + threadIdx.x;
    if (i < K * DD) {
        int j = i & (DD - 1);
        float s = g[j] * rsqrtf(v[j] + 1e-5f);
        g_wf[wdst + i] = W[i] * s;
    }
    if (i < DD) {
        float s = g[i] * rsqrtf(v[i] + 1e-5f);
        g_wf[bdst + i] = (b[i] - m[i]) * s + be[i];
    }
}

// ---------------- fused GEMM kernel ----------------
// MODE 0: h = x @ Win + b_in                          (K1=64, single GEMM)
// MODE 1: m = relu(bn(A1@Wm1)); m = relu(bn(m@Wm2));  scatter-add to agg
//         A1 = [h[dst] | h[src] | ea]                 (K1=272, K2=128)
// MODE 2: u = relu(bn([h|agg]@Wu1)); u = relu(bn(u@Wu2)); out = h + u
//                                                     (K1=256, K2=128)
#define BM  128
#define BK  8
#define ASTRIDE 132   // padded row stride for As / M1

template <int MODE>
__global__ __launch_bounds__(256)
void gemm_kernel(const float* __restrict__ x,
                 const int*   __restrict__ eidx,
                 const float* __restrict__ ea,
                 const float* __restrict__ Win,
                 const float* __restrict__ bin,
                 int layer, float* __restrict__ dout)
{
    extern __shared__ float smem[];
    float* As = smem;                       // BK * 132
    float* Bs = As + BK * ASTRIDE;          // BK * 128
    float* M1 = Bs + BK * 128;              // 128 * 132 (modes 1,2)
    int*   sdst = (int*)(M1 + 128 * ASTRIDE);
    int*   ssrc = sdst + 128;

    const int tid = threadIdx.x;
    const int tx = tid & 15;
    const int ty = tid >> 4;
    const int row0 = blockIdx.x * BM;

    constexpr int K1 = (MODE == 0) ? DINP : (MODE == 1 ? (2 * DD + DEA) : 2 * DD);

    const float* W1;
    const float* B1;
    if (MODE == 0) { W1 = Win; B1 = bin; }
    else if (MODE == 1) { W1 = g_wf + (size_t)layer * LSTR + WM1_OFF; B1 = g_wf + (size_t)layer * LSTR + BM1_OFF; }
    else { W1 = g_wf + (size_t)layer * LSTR + WU1_OFF; B1 = g_wf + (size_t)layer * LSTR + BU1_OFF; }

    // per-thread A-load coords: one float4 per chunk
    const int el   = tid >> 1;          // tile row 0..127
    const int koff = (tid & 1) << 2;    // 0 or 4

    // per-thread B-load coords
    const int bk = tid >> 5;            // 0..7
    const int bc = (tid & 31) << 2;     // 0..124

    // gather setup
    const float* pdst = nullptr;
    const float* psrc = nullptr;
    const float* pea  = nullptr;
    const float* pnode = nullptr;
    if (MODE == 1) {
        if (tid < 128) {
            int e = row0 + tid;
            int ec = e < NE ? e : NE - 1;
            ssrc[tid] = eidx[ec];
            sdst[tid] = eidx[NE + ec];
        }
        __syncthreads();
        int ec = row0 + el; if (ec >= NE) ec = NE - 1;
        pdst = g_h + (size_t)sdst[el] * DD;
        psrc = g_h + (size_t)ssrc[el] * DD;
        pea  = ea  + (size_t)ec * DEA;
    } else {
        int rc = row0 + el;
        int cl = rc < NN ? rc : NN - 1;
        if (MODE == 0) pnode = x + (size_t)cl * DINP;
        else           pnode = g_h + (size_t)cl * DD;   // agg handled via offset below
    }
    const int rcl = (MODE != 1) ? ((row0 + el < NN) ? (row0 + el) : (NN - 1)) : 0;

    // output row indices for this thread's 8x8 microtile
    int rr[8];
#pragma unroll
    for (int i = 0; i < 4; i++) { rr[i] = ty * 4 + i; rr[i + 4] = 64 + ty * 4 + i; }

    float acc[8][8];
#pragma unroll
    for (int i = 0; i < 8; i++)
#pragma unroll
        for (int j = 0; j < 8; j++) acc[i][j] = 0.f;

    // ---------------- GEMM 1 ----------------
#pragma unroll 1
    for (int kc = 0; kc < K1 / BK; kc++) {
        const int k0 = kc * BK;
        // load A chunk (gathered), transpose into As[k][row]
        {
            int k = k0 + koff;
            const float* p;
            if (MODE == 1) {
                p = (k < DD) ? (pdst + k) : (k < 2 * DD) ? (psrc + (k - DD)) : (pea + (k - 2 * DD));
            } else if (MODE == 0) {
                p = pnode + k;
            } else {
                p = (k < DD) ? (pnode + k) : (g_agg + (size_t)rcl * DD + (k - DD));
            }
            float4 v = *reinterpret_cast<const float4*>(p);
            As[(koff + 0) * ASTRIDE + el] = v.x;
            As[(koff + 1) * ASTRIDE + el] = v.y;
            As[(koff + 2) * ASTRIDE + el] = v.z;
            As[(koff + 3) * ASTRIDE + el] = v.w;
        }
        // load B chunk
        *reinterpret_cast<float4*>(&Bs[bk * 128 + bc]) =
            *reinterpret_cast<const float4*>(&W1[(size_t)(k0 + bk) * 128 + bc]);
        __syncthreads();
#pragma unroll
        for (int k = 0; k < BK; k++) {
            float4 a0 = *reinterpret_cast<const float4*>(&As[k * ASTRIDE + ty * 4]);
            float4 a1 = *reinterpret_cast<const float4*>(&As[k * ASTRIDE + 64 + ty * 4]);
            float4 b0 = *reinterpret_cast<const float4*>(&Bs[k * 128 + tx * 4]);
            float4 b1 = *reinterpret_cast<const float4*>(&Bs[k * 128 + 64 + tx * 4]);
            float av[8] = {a0.x, a0.y, a0.z, a0.w, a1.x, a1.y, a1.z, a1.w};
            float bv[8] = {b0.x, b0.y, b0.z, b0.w, b1.x, b1.y, b1.z, b1.w};
#pragma unroll
            for (int i = 0; i < 8; i++)
#pragma unroll
                for (int j = 0; j < 8; j++)
                    acc[i][j] = fmaf(av[i], bv[j], acc[i][j]);
        }
        __syncthreads();
    }

    // ---------------- epilogue 1 ----------------
    float4 bb0 = *reinterpret_cast<const float4*>(&B1[tx * 4]);
    float4 bb1 = *reinterpret_cast<const float4*>(&B1[64 + tx * 4]);

    if (MODE == 0) {
#pragma unroll
        for (int i = 0; i < 8; i++) {
            int rg = row0 + rr[i];
            if (rg < NN) {
                float4 v0 = make_float4(acc[i][0] + bb0.x, acc[i][1] + bb0.y,
                                        acc[i][2] + bb0.z, acc[i][3] + bb0.w);
                float4 v1 = make_float4(acc[i][4] + bb1.x, acc[i][5] + bb1.y,
                                        acc[i][6] + bb1.z, acc[i][7] + bb1.w);
                *reinterpret_cast<float4*>(&g_h[(size_t)rg * DD + tx * 4]) = v0;
                *reinterpret_cast<float4*>(&g_h[(size_t)rg * DD + 64 + tx * 4]) = v1;
            }
        }
        return;
    }

    // bias + relu into M1 (smem)
#pragma unroll
    for (int i = 0; i < 8; i++) {
        float4 v0 = make_float4(fmaxf(acc[i][0] + bb0.x, 0.f), fmaxf(acc[i][1] + bb0.y, 0.f),
                                fmaxf(acc[i][2] + bb0.z, 0.f), fmaxf(acc[i][3] + bb0.w, 0.f));
        float4 v1 = make_float4(fmaxf(acc[i][4] + bb1.x, 0.f), fmaxf(acc[i][5] + bb1.y, 0.f),
                                fmaxf(acc[i][6] + bb1.z, 0.f), fmaxf(acc[i][7] + bb1.w, 0.f));
        *reinterpret_cast<float4*>(&M1[rr[i] * ASTRIDE + tx * 4]) = v0;
        *reinterpret_cast<float4*>(&M1[rr[i] * ASTRIDE + 64 + tx * 4]) = v1;
    }

    // ---------------- GEMM 2 (K=128) ----------------
    const float* W2;
    const float* B2;
    if (MODE == 1) { W2 = g_wf + (size_t)layer * LSTR + WM2_OFF; B2 = g_wf + (size_t)layer * LSTR + BM2_OFF; }
    else           { W2 = g_wf + (size_t)layer * LSTR + WU2_OFF; B2 = g_wf + (size_t)layer * LSTR + BU2_OFF; }

#pragma unroll
    for (int i = 0; i < 8; i++)
#pragma unroll
        for (int j = 0; j < 8; j++) acc[i][j] = 0.f;

    const float* m1p[8];
#pragma unroll
    for (int i = 0; i < 8; i++) m1p[i] = M1 + rr[i] * ASTRIDE;

#pragma unroll 1
    for (int kc = 0; kc < DD / BK; kc++) {
        const int k0 = kc * BK;
        *reinterpret_cast<float4*>(&Bs[bk * 128 + bc]) =
            *reinterpret_cast<const float4*>(&W2[(size_t)(k0 + bk) * 128 + bc]);
        __syncthreads();
#pragma unroll
        for (int k = 0; k < BK; k++) {
            const int kk = k0 + k;
            float av[8];
#pragma unroll
            for (int i = 0; i < 8; i++) av[i] = m1p[i][kk];
            float4 b0 = *reinterpret_cast<const float4*>(&Bs[k * 128 + tx * 4]);
            float4 b1 = *reinterpret_cast<const float4*>(&Bs[k * 128 + 64 + tx * 4]);
            float bv[8] = {b0.x, b0.y, b0.z, b0.w, b1.x, b1.y, b1.z, b1.w};
#pragma unroll
            for (int i = 0; i < 8; i++)
#pragma unroll
                for (int j = 0; j < 8; j++)
                    acc[i][j] = fmaf(av[i], bv[j], acc[i][j]);
        }
        __syncthreads();
    }

    // ---------------- epilogue 2 ----------------
    float4 cb0 = *reinterpret_cast<const float4*>(&B2[tx * 4]);
    float4 cb1 = *reinterpret_cast<const float4*>(&B2[64 + tx * 4]);

    if (MODE == 1) {
#pragma unroll
        for (int i = 0; i < 8; i++) {
            int e = row0 + rr[i];
            if (e < NE) {
                float v0 = fmaxf(acc[i][0] + cb0.x, 0.f);
                float v1 = fmaxf(acc[i][1] + cb0.y, 0.f);
                float v2 = fmaxf(acc[i][2] + cb0.z, 0.f);
                float v3 = fmaxf(acc[i][3] + cb0.w, 0.f);
                float v4 = fmaxf(acc[i][4] + cb1.x, 0.f);
                float v5 = fmaxf(acc[i][5] + cb1.y, 0.f);
                float v6 = fmaxf(acc[i][6] + cb1.z, 0.f);
                float v7 = fmaxf(acc[i][7] + cb1.w, 0.f);
                float* base = g_agg + (size_t)sdst[rr[i]] * DD;
                asm volatile("red.global.add.v4.f32 [%0], {%1,%2,%3,%4};"
                             :: "l"(base + tx * 4), "f"(v0), "f"(v1), "f"(v2), "f"(v3) : "memory");
                asm volatile("red.global.add.v4.f32 [%0], {%1,%2,%3,%4};"
                             :: "l"(base + 64 + tx * 4), "f"(v4), "f"(v5), "f"(v6), "f"(v7) : "memory");
            }
        }
    } else {
        float* outp = dout ? dout : g_h;
#pragma unroll
        for (int i = 0; i < 8; i++) {
            int rg = row0 + rr[i];
            if (rg < NN) {
                float4 h0 = *reinterpret_cast<const float4*>(&g_h[(size_t)rg * DD + tx * 4]);
                float4 h1 = *reinterpret_cast<const float4*>(&g_h[(size_t)rg * DD + 64 + tx * 4]);
                float4 v0 = make_float4(h0.x + fmaxf(acc[i][0] + cb0.x, 0.f),
                                        h0.y + fmaxf(acc[i][1] + cb0.y, 0.f),
                                        h0.z + fmaxf(acc[i][2] + cb0.z, 0.f),
                                        h0.w + fmaxf(acc[i][3] + cb0.w, 0.f));
                float4 v1 = make_float4(h1.x + fmaxf(acc[i][4] + cb1.x, 0.f),
                                        h1.y + fmaxf(acc[i][5] + cb1.y, 0.f),
                                        h1.z + fmaxf(acc[i][6] + cb1.z, 0.f),
                                        h1.w + fmaxf(acc[i][7] + cb1.w, 0.f));
                *reinterpret_cast<float4*>(&outp[(size_t)rg * DD + tx * 4]) = v0;
                *reinterpret_cast<float4*>(&outp[(size_t)rg * DD + 64 + tx * 4]) = v1;
            }
        }
    }
}

// ---------------- host launcher ----------------
extern "C" void kernel_launch(void* const* d_in, const int* in_sizes, int n_in,
                              void* d_out, int out_size)
{
    const float* x    = (const float*)d_in[0];
    const int*   eidx = (const int*)d_in[1];
    const float* ea   = (const float*)d_in[2];
    const float* Win  = (const float*)d_in[3];
    const float* bin  = (const float*)d_in[4];

    struct FoldSpec { int woff, boff, K, wi, bi, gi, bei, mi, vi; };
    const FoldSpec F[4] = {
        {WM1_OFF, BM1_OFF, 2 * DD + DEA,  5,  6,  7,  8,  9, 10},
        {WM2_OFF, BM2_OFF, DD,           11, 12, 13, 14, 15, 16},
        {WU1_OFF, BU1_OFF, 2 * DD,       17, 18, 19, 20, 21, 22},
        {WU2_OFF, BU2_OFF, DD,           23, 24, 25, 26, 27, 28},
    };
    for (int l = 0; l < NLAY; l++) {
        for (int f = 0; f < 4; f++) {
            const FoldSpec& s = F[f];
            int K = s.K;
            fold_kernel<<<(K * DD + 255) / 256, 256>>>(
                (const float*)d_in[s.wi]  + (size_t)l * K * DD,
                (const float*)d_in[s.bi]  + (size_t)l * DD,
                (const float*)d_in[s.gi]  + (size_t)l * DD,
                (const float*)d_in[s.bei] + (size_t)l * DD,
                (const float*)d_in[s.mi]  + (size_t)l * DD,
                (const float*)d_in[s.vi]  + (size_t)l * DD,
                s.woff + l * LSTR, s.boff + l * LSTR, K);
        }
    }

    const size_t smem0  = (size_t)(BK * ASTRIDE + BK * 128) * 4;
    const size_t smem12 = (size_t)(BK * ASTRIDE + BK * 128 + 128 * ASTRIDE) * 4 + 256 * 4;

    cudaFuncSetAttribute(gemm_kernel<0>, cudaFuncAttributeMaxDynamicSharedMemorySize, (int)smem12);
    cudaFuncSetAttribute(gemm_kernel<1>, cudaFuncAttributeMaxDynamicSharedMemorySize, (int)smem12);
    cudaFuncSetAttribute(gemm_kernel<2>, cudaFuncAttributeMaxDynamicSharedMemorySize, (int)smem12);

    const int nodeTiles = (NN + BM - 1) / BM;   // 391
    const int edgeTiles = (NE + BM - 1) / BM;   // 3907

    // h = x @ Win + b_in
    gemm_kernel<0><<<nodeTiles, 256, smem0>>>(x, nullptr, nullptr, Win, bin, 0, nullptr);

    for (int l = 0; l < NLAY; l++) {
        zero_agg_kernel<<<(NN * DD / 4 + 255) / 256, 256>>>();
        gemm_kernel<1><<<edgeTiles, 256, smem12>>>(x, eidx, ea, nullptr, nullptr, l, nullptr);
        gemm_kernel<2><<<nodeTiles, 256, smem12>>>(x, nullptr, nullptr, nullptr, nullptr, l,
                                                   (l == NLAY - 1) ? (float*)d_out : nullptr);
    }
}

// round 3
// speedup vs baseline: 1.0020x; 1.0020x over previous
#include <cuda_runtime.h>
#include <cstdint>

// ---------------- problem constants ----------------
#define NN   50000
#define NE   500000
#define DD   128
#define DEA  16
#define DINP 64
#define NLAY 4

// folded-weight buffer layout (floats, per layer)
#define LSTR     100864
#define WM1_OFF  0
#define BM1_OFF  34816
#define WM2_OFF  34944
#define BM2_OFF  51328
#define WU1_OFF  51456
#define BU1_OFF  84224
#define WU2_OFF  84352
#define BU2_OFF  100736

// ---------------- device scratch (no allocs allowed) ----------------
__device__ __align__(16) float g_h[(size_t)NN * DD];
__device__ __align__(16) float g_agg[(size_t)NN * DD];
__device__ __align__(16) float g_wf[(size_t)NLAY * LSTR];

// ---------------- zero agg ----------------
__global__ void zero_agg_kernel() {
    int i = blockIdx.x * blockDim.x + threadIdx.x;
    float4 z = make_float4(0.f, 0.f, 0.f, 0.f);
    if (i < NN * DD / 4) reinterpret_cast<float4*>(g_agg)[i] = z;
}

// ---------------- fold BN into linear ----------------
__global__ void fold_kernel(const float* __restrict__ W, const float* __restrict__ b,
                            const float* __restrict__ g, const float* __restrict__ be,
                            const float* __restrict__ m, const float* __restrict__ v,
                            int wdst, int bdst, int K) {
    int i = blockIdx.x * blockDim.x + threadIdx.x;
    if (i < K * DD) {
        int j = i & (DD - 1);
        float s = g[j] * rsqrtf(v[j] + 1e-5f);
        g_wf[wdst + i] = W[i] * s;
    }
    if (i < DD) {
        float s = g[i] * rsqrtf(v[i] + 1e-5f);
        g_wf[bdst + i] = (b[i] - m[i]) * s + be[i];
    }
}

// ---------------- fused GEMM kernel ----------------
// MODE 0: h = x @ Win + b_in                          (K1=64, single GEMM)
// MODE 1: m = relu(bn(A1@Wm1)); m = relu(bn(m@Wm2));  scatter-add to agg
//         A1 = [h[dst] | h[src] | ea]                 (K1=272, K2=128)
// MODE 2: u = relu(bn([h|agg]@Wu1)); u = relu(bn(u@Wu2)); out = h + u
//                                                     (K1=256, K2=128)
#define BM  128
#define BK  8
#define ASTRIDE 132   // padded row stride for As / M1

template <int MODE>
__global__ __launch_bounds__(256)
void gemm_kernel(const float* __restrict__ x,
                 const int*   __restrict__ eidx,
                 const float* __restrict__ ea,
                 const float* __restrict__ Win,
                 const float* __restrict__ bin,
                 int layer, float* __restrict__ dout)
{
    extern __shared__ float smem[];
    float* As = smem;                       // BK * 132
    float* Bs = As + BK * ASTRIDE;          // BK * 128
    float* M1 = Bs + BK * 128;              // 128 * 132 (modes 1,2)
    int*   sdst = (int*)(M1 + 128 * ASTRIDE);
    int*   ssrc = sdst + 128;

    const int tid = threadIdx.x;
    const int tx = tid & 15;
    const int ty = tid >> 4;
    const int row0 = blockIdx.x * BM;

    constexpr int K1 = (MODE == 0) ? DINP : (MODE == 1 ? (2 * DD + DEA) : 2 * DD);

    const float* W1;
    const float* B1;
    if (MODE == 0) { W1 = Win; B1 = bin; }
    else if (MODE == 1) { W1 = g_wf + (size_t)layer * LSTR + WM1_OFF; B1 = g_wf + (size_t)layer * LSTR + BM1_OFF; }
    else { W1 = g_wf + (size_t)layer * LSTR + WU1_OFF; B1 = g_wf + (size_t)layer * LSTR + BU1_OFF; }

    // per-thread A-load coords: one float4 per chunk
    const int el   = tid >> 1;          // tile row 0..127
    const int koff = (tid & 1) << 2;    // 0 or 4

    // per-thread B-load coords
    const int bk = tid >> 5;            // 0..7
    const int bc = (tid & 31) << 2;     // 0..124

    // gather setup
    const float* pdst = nullptr;
    const float* psrc = nullptr;
    const float* pea  = nullptr;
    const float* pnode = nullptr;
    if (MODE == 1) {
        if (tid < 128) {
            int e = row0 + tid;
            int ec = e < NE ? e : NE - 1;
            ssrc[tid] = eidx[ec];
            sdst[tid] = eidx[NE + ec];
        }
        __syncthreads();
        int ec = row0 + el; if (ec >= NE) ec = NE - 1;
        pdst = g_h + (size_t)sdst[el] * DD;
        psrc = g_h + (size_t)ssrc[el] * DD;
        pea  = ea  + (size_t)ec * DEA;
    } else {
        int rc = row0 + el;
        int cl = rc < NN ? rc : NN - 1;
        if (MODE == 0) pnode = x + (size_t)cl * DINP;
        else           pnode = g_h + (size_t)cl * DD;   // agg handled via offset below
    }
    const int rcl = (MODE != 1) ? ((row0 + el < NN) ? (row0 + el) : (NN - 1)) : 0;

    // output row indices for this thread's 8x8 microtile
    int rr[8];
#pragma unroll
    for (int i = 0; i < 4; i++) { rr[i] = ty * 4 + i; rr[i + 4] = 64 + ty * 4 + i; }

    float acc[8][8];
#pragma unroll
    for (int i = 0; i < 8; i++)
#pragma unroll
        for (int j = 0; j < 8; j++) acc[i][j] = 0.f;

    // ---------------- GEMM 1 ----------------
#pragma unroll 1
    for (int kc = 0; kc < K1 / BK; kc++) {
        const int k0 = kc * BK;
        // load A chunk (gathered), transpose into As[k][row]
        {
            int k = k0 + koff;
            const float* p;
            if (MODE == 1) {
                p = (k < DD) ? (pdst + k) : (k < 2 * DD) ? (psrc + (k - DD)) : (pea + (k - 2 * DD));
            } else if (MODE == 0) {
                p = pnode + k;
            } else {
                p = (k < DD) ? (pnode + k) : (g_agg + (size_t)rcl * DD + (k - DD));
            }
            float4 v = *reinterpret_cast<const float4*>(p);
            As[(koff + 0) * ASTRIDE + el] = v.x;
            As[(koff + 1) * ASTRIDE + el] = v.y;
            As[(koff + 2) * ASTRIDE + el] = v.z;
            As[(koff + 3) * ASTRIDE + el] = v.w;
        }
        // load B chunk
        *reinterpret_cast<float4*>(&Bs[bk * 128 + bc]) =
            *reinterpret_cast<const float4*>(&W1[(size_t)(k0 + bk) * 128 + bc]);
        __syncthreads();
#pragma unroll
        for (int k = 0; k < BK; k++) {
            float4 a0 = *reinterpret_cast<const float4*>(&As[k * ASTRIDE + ty * 4]);
            float4 a1 = *reinterpret_cast<const float4*>(&As[k * ASTRIDE + 64 + ty * 4]);
            float4 b0 = *reinterpret_cast<const float4*>(&Bs[k * 128 + tx * 4]);
            float4 b1 = *reinterpret_cast<const float4*>(&Bs[k * 128 + 64 + tx * 4]);
            float av[8] = {a0.x, a0.y, a0.z, a0.w, a1.x, a1.y, a1.z, a1.w};
            float bv[8] = {b0.x, b0.y, b0.z, b0.w, b1.x, b1.y, b1.z, b1.w};
#pragma unroll
            for (int i = 0; i < 8; i++)
#pragma unroll
                for (int j = 0; j < 8; j++)
                    acc[i][j] = fmaf(av[i], bv[j], acc[i][j]);
        }
        __syncthreads();
    }

    // ---------------- epilogue 1 ----------------
    float4 bb0 = *reinterpret_cast<const float4*>(&B1[tx * 4]);
    float4 bb1 = *reinterpret_cast<const float4*>(&B1[64 + tx * 4]);

    if (MODE == 0) {
#pragma unroll
        for (int i = 0; i < 8; i++) {
            int rg = row0 + rr[i];
            if (rg < NN) {
                float4 v0 = make_float4(acc[i][0] + bb0.x, acc[i][1] + bb0.y,
                                        acc[i][2] + bb0.z, acc[i][3] + bb0.w);
                float4 v1 = make_float4(acc[i][4] + bb1.x, acc[i][5] + bb1.y,
                                        acc[i][6] + bb1.z, acc[i][7] + bb1.w);
                *reinterpret_cast<float4*>(&g_h[(size_t)rg * DD + tx * 4]) = v0;
                *reinterpret_cast<float4*>(&g_h[(size_t)rg * DD + 64 + tx * 4]) = v1;
            }
        }
        return;
    }

    // bias + relu into M1 (smem)
#pragma unroll
    for (int i = 0; i < 8; i++) {
        float4 v0 = make_float4(fmaxf(acc[i][0] + bb0.x, 0.f), fmaxf(acc[i][1] + bb0.y, 0.f),
                                fmaxf(acc[i][2] + bb0.z, 0.f), fmaxf(acc[i][3] + bb0.w, 0.f));
        float4 v1 = make_float4(fmaxf(acc[i][4] + bb1.x, 0.f), fmaxf(acc[i][5] + bb1.y, 0.f),
                                fmaxf(acc[i][6] + bb1.z, 0.f), fmaxf(acc[i][7] + bb1.w, 0.f));
        *reinterpret_cast<float4*>(&M1[rr[i] * ASTRIDE + tx * 4]) = v0;
        *reinterpret_cast<float4*>(&M1[rr[i] * ASTRIDE + 64 + tx * 4]) = v1;
    }

    // ---------------- GEMM 2 (K=128) ----------------
    const float* W2;
    const float* B2;
    if (MODE == 1) { W2 = g_wf + (size_t)layer * LSTR + WM2_OFF; B2 = g_wf + (size_t)layer * LSTR + BM2_OFF; }
    else           { W2 = g_wf + (size_t)layer * LSTR + WU2_OFF; B2 = g_wf + (size_t)layer * LSTR + BU2_OFF; }

#pragma unroll
    for (int i = 0; i < 8; i++)
#pragma unroll
        for (int j = 0; j < 8; j++) acc[i][j] = 0.f;

    const float* m1p[8];
#pragma unroll
    for (int i = 0; i < 8; i++) m1p[i] = M1 + rr[i] * ASTRIDE;

#pragma unroll 1
    for (int kc = 0; kc < DD / BK; kc++) {
        const int k0 = kc * BK;
        *reinterpret_cast<float4*>(&Bs[bk * 128 + bc]) =
            *reinterpret_cast<const float4*>(&W2[(size_t)(k0 + bk) * 128 + bc]);
        __syncthreads();
#pragma unroll
        for (int k = 0; k < BK; k++) {
            const int kk = k0 + k;
            float av[8];
#pragma unroll
            for (int i = 0; i < 8; i++) av[i] = m1p[i][kk];
            float4 b0 = *reinterpret_cast<const float4*>(&Bs[k * 128 + tx * 4]);
            float4 b1 = *reinterpret_cast<const float4*>(&Bs[k * 128 + 64 + tx * 4]);
            float bv[8] = {b0.x, b0.y, b0.z, b0.w, b1.x, b1.y, b1.z, b1.w};
#pragma unroll
            for (int i = 0; i < 8; i++)
#pragma unroll
                for (int j = 0; j < 8; j++)
                    acc[i][j] = fmaf(av[i], bv[j], acc[i][j]);
        }
        __syncthreads();
    }

    // ---------------- epilogue 2 ----------------
    float4 cb0 = *reinterpret_cast<const float4*>(&B2[tx * 4]);
    float4 cb1 = *reinterpret_cast<const float4*>(&B2[64 + tx * 4]);

    if (MODE == 1) {
#pragma unroll
        for (int i = 0; i < 8; i++) {
            int e = row0 + rr[i];
            if (e < NE) {
                float v0 = fmaxf(acc[i][0] + cb0.x, 0.f);
                float v1 = fmaxf(acc[i][1] + cb0.y, 0.f);
                float v2 = fmaxf(acc[i][2] + cb0.z, 0.f);
                float v3 = fmaxf(acc[i][3] + cb0.w, 0.f);
                float v4 = fmaxf(acc[i][4] + cb1.x, 0.f);
                float v5 = fmaxf(acc[i][5] + cb1.y, 0.f);
                float v6 = fmaxf(acc[i][6] + cb1.z, 0.f);
                float v7 = fmaxf(acc[i][7] + cb1.w, 0.f);
                float* base = g_agg + (size_t)sdst[rr[i]] * DD;
                asm volatile("red.global.add.v4.f32 [%0], {%1,%2,%3,%4};"
                             :: "l"(base + tx * 4), "f"(v0), "f"(v1), "f"(v2), "f"(v3) : "memory");
                asm volatile("red.global.add.v4.f32 [%0], {%1,%2,%3,%4};"
                             :: "l"(base + 64 + tx * 4), "f"(v4), "f"(v5), "f"(v6), "f"(v7) : "memory");
            }
        }
    } else {
        float* outp = dout ? dout : g_h;
#pragma unroll
        for (int i = 0; i < 8; i++) {
            int rg = row0 + rr[i];
            if (rg < NN) {
                float4 h0 = *reinterpret_cast<const float4*>(&g_h[(size_t)rg * DD + tx * 4]);
                float4 h1 = *reinterpret_cast<const float4*>(&g_h[(size_t)rg * DD + 64 + tx * 4]);
                float4 v0 = make_float4(h0.x + fmaxf(acc[i][0] + cb0.x, 0.f),
                                        h0.y + fmaxf(acc[i][1] + cb0.y, 0.f),
                                        h0.z + fmaxf(acc[i][2] + cb0.z, 0.f),
                                        h0.w + fmaxf(acc[i][3] + cb0.w, 0.f));
                float4 v1 = make_float4(h1.x + fmaxf(acc[i][4] + cb1.x, 0.f),
                                        h1.y + fmaxf(acc[i][5] + cb1.y, 0.f),
                                        h1.z + fmaxf(acc[i][6] + cb1.z, 0.f),
                                        h1.w + fmaxf(acc[i][7] + cb1.w, 0.f));
                *reinterpret_cast<float4*>(&outp[(size_t)rg * DD + tx * 4]) = v0;
                *reinterpret_cast<float4*>(&outp[(size_t)rg * DD + 64 + tx * 4]) = v1;
            }
        }
    }
}

// ---------------- host launcher ----------------
extern "C" void kernel_launch(void* const* d_in, const int* in_sizes, int n_in,
                              void* d_out, int out_size)
{
    const float* x    = (const float*)d_in[0];
    const int*   eidx = (const int*)d_in[1];
    const float* ea   = (const float*)d_in[2];
    const float* Win  = (const float*)d_in[3];
    const float* bin  = (const float*)d_in[4];

    struct FoldSpec { int woff, boff, K, wi, bi, gi, bei, mi, vi; };
    const FoldSpec F[4] = {
        {WM1_OFF, BM1_OFF, 2 * DD + DEA,  5,  6,  7,  8,  9, 10},
        {WM2_OFF, BM2_OFF, DD,           11, 12, 13, 14, 15, 16},
        {WU1_OFF, BU1_OFF, 2 * DD,       17, 18, 19, 20, 21, 22},
        {WU2_OFF, BU2_OFF, DD,           23, 24, 25, 26, 27, 28},
    };
    for (int l = 0; l < NLAY; l++) {
        for (int f = 0; f < 4; f++) {
            const FoldSpec& s = F[f];
            int K = s.K;
            fold_kernel<<<(K * DD + 255) / 256, 256>>>(
                (const float*)d_in[s.wi]  + (size_t)l * K * DD,
                (const float*)d_in[s.bi]  + (size_t)l * DD,
                (const float*)d_in[s.gi]  + (size_t)l * DD,
                (const float*)d_in[s.bei] + (size_t)l * DD,
                (const float*)d_in[s.mi]  + (size_t)l * DD,
                (const float*)d_in[s.vi]  + (size_t)l * DD,
                s.woff + l * LSTR, s.boff + l * LSTR, K);
        }
    }

    const size_t smem0  = (size_t)(BK * ASTRIDE + BK * 128) * 4;
    const size_t smem12 = (size_t)(BK * ASTRIDE + BK * 128 + 128 * ASTRIDE) * 4 + 256 * 4;

    cudaFuncSetAttribute(gemm_kernel<0>, cudaFuncAttributeMaxDynamicSharedMemorySize, (int)smem12);
    cudaFuncSetAttribute(gemm_kernel<1>, cudaFuncAttributeMaxDynamicSharedMemorySize, (int)smem12);
    cudaFuncSetAttribute(gemm_kernel<2>, cudaFuncAttributeMaxDynamicSharedMemorySize, (int)smem12);

    const int nodeTiles = (NN + BM - 1) / BM;   // 391
    const int edgeTiles = (NE + BM - 1) / BM;   // 3907

    // h = x @ Win + b_in
    gemm_kernel<0><<<nodeTiles, 256, smem0>>>(x, nullptr, nullptr, Win, bin, 0, nullptr);

    for (int l = 0; l < NLAY; l++) {
        zero_agg_kernel<<<(NN * DD / 4 + 255) / 256, 256>>>();
        gemm_kernel<1><<<edgeTiles, 256, smem12>>>(x, eidx, ea, nullptr, nullptr, l, nullptr);
        gemm_kernel<2><<<nodeTiles, 256, smem12>>>(x, nullptr, nullptr, nullptr, nullptr, l,
                                                   (l == NLAY - 1) ? (float*)d_out : nullptr);
    }
}